// round 1
// baseline (speedup 1.0000x reference)
#include <cuda_runtime.h>
#include <cstdint>
#include <math.h>

// Problem constants
#define Bb   256
#define Tt   1024
#define Ii   8
#define Hh   164
#define JH   82          // H/2 : hidden slice per CTA (M-split)
#define LG   328         // 4*JH gate rows per CTA
#define NTH  352         // 11 warps
#define NCTA 128         // 64 clusters x 2

// shared memory layout (bytes)
#define OFF_WS     0
#define SZ_WS      (Hh * LG * 4)           // 215168: Ws[k][lg] transposed
#define OFF_HQ     (OFF_WS + SZ_WS)        // 16-aligned (215168 % 16 == 0)
#define SZ_HQ      (2 * Hh * 16)           // double-buffered h as float4 over 4 rows
#define OFF_GATES  (OFF_HQ + SZ_HQ)
#define SZ_GATES   (LG * 16)               // gates4[lg] = float4 over rows
#define OFF_PREDC  (OFF_GATES + SZ_GATES)
#define SZ_PREDC   (LG * 4)
#define OFF_WOUT   (OFF_PREDC + SZ_PREDC)
#define SZ_WOUT    (JH * 4)
#define OFF_XQ     ((OFF_WOUT + SZ_WOUT + 15) & ~15)
#define SZ_XQ      (Ii * 16)               // x as float4 over rows, [i]
#define OFF_PP     (OFF_XQ + SZ_XQ)
#define SZ_PP      (2 * 2 * 4 * 4)         // predpart[parity][rank][row]
#define OFF_PF     (OFF_PP + SZ_PP)
#define SZ_PF      (2 * 4 * 4)             // predfinal[parity][row]
#define SMEM_TOTAL (OFF_PF + SZ_PF)        // 227536 <= 232448

__device__ __forceinline__ float sigmoidf_(float v) {
    return 1.0f / (1.0f + expf(-v));
}

__device__ __forceinline__ unsigned long long pack2_(float a, float b) {
    unsigned long long r;
    asm("mov.b64 %0, {%1, %2};" : "=l"(r) : "f"(a), "f"(b));
    return r;
}
__device__ __forceinline__ void unpack2_(unsigned long long v, float& a, float& b) {
    asm("mov.b64 {%0, %1}, %2;" : "=f"(a), "=f"(b) : "l"(v));
}

// remote (peer-CTA) shared-memory scalar store via DSMEM
__device__ __forceinline__ void st_remote_f32(uint32_t local_addr, uint32_t peer, float v) {
    uint32_t ra;
    asm("mapa.shared::cluster.u32 %0, %1, %2;" : "=r"(ra) : "r"(local_addr), "r"(peer));
    asm volatile("st.shared::cluster.f32 [%0], %1;" :: "r"(ra), "f"(v) : "memory");
}

extern "C" __global__ void __launch_bounds__(NTH, 1) __cluster_dims__(2, 1, 1)
lstm_anom_kernel(const float* __restrict__ x,
                 const float* __restrict__ Wih,
                 const float* __restrict__ Whh,
                 const float* __restrict__ bih,
                 const float* __restrict__ bhh,
                 const float* __restrict__ Wout,
                 const float* __restrict__ bout,
                 float* __restrict__ out)
{
    extern __shared__ char smem[];
    float*  Ws     = (float*)(smem + OFF_WS);     // [k*LG + lg]
    float4* hq     = (float4*)(smem + OFF_HQ);    // [buf*Hh + k] rows packed
    float4* gates4 = (float4*)(smem + OFF_GATES); // [lg]
    float*  predc  = (float*)(smem + OFF_PREDC);  // [jj*4 + r]
    float*  wout_s = (float*)(smem + OFF_WOUT);   // [jj]
    float*  xqf    = (float*)(smem + OFF_XQ);     // [i*4 + r]
    float*  pp     = (float*)(smem + OFF_PP);     // [(par*2+rank)*4 + r]
    float*  pf     = (float*)(smem + OFF_PF);     // [par*4 + r]

    const int tid     = threadIdx.x;
    const uint32_t rank = (uint32_t)(blockIdx.x & 1);   // == cluster_ctarank for (2,1,1)
    const uint32_t peer = rank ^ 1u;
    const int cluster = blockIdx.x >> 1;
    const int row0    = cluster * 4;

    const uint32_t smem_b = (uint32_t)__cvta_generic_to_shared(smem);

    // ---- load W_hh slice into smem, transposed: Ws[k*LG + lg] ----
    for (int idx = tid; idx < LG * Hh; idx += NTH) {
        int lg = idx / Hh;
        int k  = idx - lg * Hh;
        int gt = lg / JH;
        int jj = lg - gt * JH;
        int R  = gt * Hh + (int)rank * JH + jj;     // global gate row
        Ws[k * LG + lg] = Whh[R * Hh + k];
    }
    if (tid < JH) wout_s[tid] = Wout[(int)rank * JH + tid];
    if (tid < Hh) hq[tid] = make_float4(0.f, 0.f, 0.f, 0.f);  // h buffer 0 = zeros
    const float bout_r = bout[0];

    // per-thread W_ih row + bias (thread lg)
    float wih_r[Ii];
    float bias_r = 0.f;
    if (tid < LG) {
        int gt = tid / JH;
        int jj = tid - gt * JH;
        int R  = gt * Hh + (int)rank * JH + jj;
#pragma unroll
        for (int i = 0; i < Ii; i++) wih_r[i] = Wih[R * Ii + i];
        bias_r = bih[R] + bhh[R];
    }
    float c_r = 0.f;   // cell state for update mapping: tid -> (jj = tid>>2, r = tid&3)

    __syncthreads();
    asm volatile("barrier.cluster.arrive.aligned;" ::: "memory");
    asm volatile("barrier.cluster.wait.aligned;" ::: "memory");

    for (int t = 0; t < Tt; ++t) {
        const int cur = t & 1;
        const int nxt = cur ^ 1;

        // ---- phase 0: load x_t, apply anomaly replacement on feature 0, emit flag ----
        if (tid < 32) {
            int r = tid >> 3, i = tid & 7;
            int row = row0 + r;
            float xv = x[((size_t)(row * Tt + t)) * Ii + i];
            if (i == 0) {
                float flag = 0.f;
                if (t > 0) {
                    float pprev = pf[nxt * 4 + r];          // pred from step t-1
                    if (fabsf(pprev - xv) > 0.1f) { xv = pprev; flag = 1.f; }
                }
                if (rank == 0) out[(size_t)Bb * Tt + (size_t)row * Tt + t] = flag;
            }
            xqf[i * 4 + r] = xv;
        }
        __syncthreads();

        // ---- phase 1: gate accumulation (f32x2 packed FMA over 4 rows) ----
        if (tid < LG) {
            float a0 = bias_r, a1 = bias_r, a2 = bias_r, a3 = bias_r;
            const float4* xq4 = (const float4*)xqf;
#pragma unroll
            for (int i = 0; i < Ii; i++) {
                float4 xv = xq4[i];
                a0 += wih_r[i] * xv.x;  a1 += wih_r[i] * xv.y;
                a2 += wih_r[i] * xv.z;  a3 += wih_r[i] * xv.w;
            }
            unsigned long long acc01 = pack2_(a0, a1);
            unsigned long long acc23 = pack2_(a2, a3);
            const ulonglong2* hp = (const ulonglong2*)(hq + cur * Hh);
            const float* wp = Ws + tid;
#pragma unroll 8
            for (int k = 0; k < Hh; k++) {
                float w = wp[k * LG];
                ulonglong2 h2 = hp[k];
                unsigned long long w2;
                asm("mov.b64 %0, {%1, %1};" : "=l"(w2) : "f"(w));
                asm("fma.rn.f32x2 %0, %1, %2, %0;" : "+l"(acc01) : "l"(w2), "l"(h2.x));
                asm("fma.rn.f32x2 %0, %1, %2, %0;" : "+l"(acc23) : "l"(w2), "l"(h2.y));
            }
            unpack2_(acc01, a0, a1);
            unpack2_(acc23, a2, a3);
            gates4[tid] = make_float4(a0, a1, a2, a3);
        }
        __syncthreads();

        // ---- phase 2: activations, (c,h) update, h exchange, pred contributions ----
        if (tid < LG) {
            int jj = tid >> 2, r = tid & 3;
            const float* gf_ = (const float*)gates4;
            float gi = gf_[(0 * JH + jj) * 4 + r];
            float gF = gf_[(1 * JH + jj) * 4 + r];
            float gg = gf_[(2 * JH + jj) * 4 + r];
            float go = gf_[(3 * JH + jj) * 4 + r];
            float iv = sigmoidf_(gi);
            float fv = sigmoidf_(gF);
            float gv = tanhf(gg);
            float ov = sigmoidf_(go);
            c_r = fv * c_r + iv * gv;
            float hn = ov * tanhf(c_r);

            int kg = (int)rank * JH + jj;                 // global hidden index
            ((float*)hq)[(nxt * Hh + kg) * 4 + r] = hn;   // own smem
            st_remote_f32(smem_b + OFF_HQ + (uint32_t)((nxt * Hh + kg) * 16 + r * 4),
                          peer, hn);                       // peer smem
            predc[tid] = hn * wout_s[jj];
        }
        __syncthreads();

        // ---- phase 3: per-row pred partial reduction (4 warps) ----
        if (tid < 128) {
            int r = tid >> 5, lane = tid & 31;
            float s = 0.f;
            for (int jj = lane; jj < JH; jj += 32) s += predc[jj * 4 + r];
#pragma unroll
            for (int o = 16; o > 0; o >>= 1) s += __shfl_down_sync(0xffffffffu, s, o);
            if (lane == 0) {
                int pidx = (cur * 2 + (int)rank) * 4 + r;
                pp[pidx] = s;
                st_remote_f32(smem_b + OFF_PP + (uint32_t)(pidx * 4), peer, s);
            }
        }

        // ---- phase 4: cluster barrier (h halves + pred partials exchanged) ----
        asm volatile("barrier.cluster.arrive.aligned;" ::: "memory");
        asm volatile("barrier.cluster.wait.aligned;" ::: "memory");

        // ---- phase 5: final pred, write outputs ----
        if (tid < 4) {
            float pred = pp[(cur * 2 + 0) * 4 + tid] + pp[(cur * 2 + 1) * 4 + tid] + bout_r;
            pf[cur * 4 + tid] = pred;
            if (rank == 0) out[(size_t)(row0 + tid) * Tt + t] = pred;
        }
        __syncthreads();
    }
}

extern "C" void kernel_launch(void* const* d_in, const int* in_sizes, int n_in,
                              void* d_out, int out_size) {
    (void)in_sizes; (void)n_in; (void)out_size;
    cudaFuncSetAttribute(lstm_anom_kernel,
                         cudaFuncAttributeMaxDynamicSharedMemorySize, SMEM_TOTAL);
    lstm_anom_kernel<<<NCTA, NTH, SMEM_TOTAL>>>(
        (const float*)d_in[0],   // x
        (const float*)d_in[1],   // W_ih
        (const float*)d_in[2],   // W_hh
        (const float*)d_in[3],   // b_ih
        (const float*)d_in[4],   // b_hh
        (const float*)d_in[5],   // W_out
        (const float*)d_in[6],   // b_out
        (float*)d_out);
}

// round 2
// speedup vs baseline: 1.0587x; 1.0587x over previous
#include <cuda_runtime.h>
#include <cstdint>
#include <math.h>

// Problem constants
#define Bb   256
#define Tt   1024
#define Ii   8
#define Hh   164
#define JH   82          // hidden slice per CTA (M-split across 2-CTA cluster)
#define KP   82          // k-pairs (Hh/2)
#define WR   40          // k-pairs held in registers per gate row
#define WS   (KP - WR)   // 42 k-pairs in shared memory
#define NTH  192         // 6 warps; 164 active in compute phases
#define NCTA 128         // 64 clusters x 2

// shared memory layout (bytes)
#define OFF_WSM   0
#define SZ_WSM    (WS * 2 * 164 * 8)          // 110208: Wsm[kk-WR][rowsel][tid] as u64 pairs
#define OFF_HQ    (OFF_WSM + SZ_WSM)          // 110208 (16-aligned)
#define SZ_HQ     (2 * KP * 32)               // 5248: double-buffered h, 32B per k-pair (4 rows x float2)
#define OFF_GATES (OFF_HQ + SZ_HQ)
#define SZ_GATES  (328 * 16)                  // gates4[lg] = float4 over batch rows
#define OFF_PREDC (OFF_GATES + SZ_GATES)
#define SZ_PREDC  (328 * 4)
#define OFF_WOUT  (OFF_PREDC + SZ_PREDC)
#define SZ_WOUT   (JH * 4)
#define OFF_WIH   ((OFF_WOUT + SZ_WOUT + 15) & ~15)
#define SZ_WIH    (328 * Ii * 4)              // 10496
#define OFF_XQ    (OFF_WIH + SZ_WIH)
#define SZ_XQ     (Ii * 16)                   // x as float4 over rows, [i]
#define OFF_PP    (OFF_XQ + SZ_XQ)
#define SZ_PP     (2 * 2 * 4 * 4)             // predpart[parity][rank][row]
#define OFF_MBAR  (OFF_PP + SZ_PP)
#define SZ_MBAR   16                          // two mbarriers
#define SMEM_TOTAL (OFF_MBAR + SZ_MBAR)       // 133056

typedef unsigned long long ull;

__device__ __forceinline__ float sigmoidf_(float v) {
    return 1.0f / (1.0f + expf(-v));
}
__device__ __forceinline__ ull pack2_(float a, float b) {
    ull r; asm("mov.b64 %0, {%1, %2};" : "=l"(r) : "f"(a), "f"(b)); return r;
}
__device__ __forceinline__ void unpack2_(ull v, float& a, float& b) {
    asm("mov.b64 {%0, %1}, %2;" : "=f"(a), "=f"(b) : "l"(v));
}
__device__ __forceinline__ void fma2_(ull& acc, ull a, ull b) {
    asm("fma.rn.f32x2 %0, %1, %2, %0;" : "+l"(acc) : "l"(a), "l"(b));
}
// remote (peer-CTA) shared-memory scalar store via DSMEM
__device__ __forceinline__ void st_remote_f32(uint32_t local_addr, uint32_t peer, float v) {
    uint32_t ra;
    asm("mapa.shared::cluster.u32 %0, %1, %2;" : "=r"(ra) : "r"(local_addr), "r"(peer));
    asm volatile("st.shared::cluster.f32 [%0], %1;" :: "r"(ra), "f"(v) : "memory");
}
// arrive (release, cluster scope) on the PEER CTA's mbarrier
__device__ __forceinline__ void mbar_arrive_peer(uint32_t local_mbar, uint32_t peer) {
    asm volatile(
        "{\n\t.reg .b32 ra;\n\t"
        "mapa.shared::cluster.u32 ra, %0, %1;\n\t"
        "mbarrier.arrive.release.cluster.shared::cluster.b64 _, [ra];\n\t}"
        :: "r"(local_mbar), "r"(peer) : "memory");
}
__device__ __forceinline__ void mbar_wait(uint32_t mbar, uint32_t parity) {
    uint32_t done;
    asm volatile(
        "{\n\t.reg .pred p;\n\t"
        "mbarrier.try_wait.parity.acquire.cluster.shared::cta.b64 p, [%1], %2;\n\t"
        "selp.b32 %0, 1, 0, p;\n\t}"
        : "=r"(done) : "r"(mbar), "r"(parity) : "memory");
    while (!done) {
        asm volatile(
            "{\n\t.reg .pred p;\n\t"
            "mbarrier.try_wait.parity.acquire.cluster.shared::cta.b64 p, [%1], %2, 0x989680;\n\t"
            "selp.b32 %0, 1, 0, p;\n\t}"
            : "=r"(done) : "r"(mbar), "r"(parity) : "memory");
    }
}

extern "C" __global__ void __launch_bounds__(NTH, 1) __cluster_dims__(2, 1, 1)
lstm_anom_kernel(const float* __restrict__ x,
                 const float* __restrict__ Wih,
                 const float* __restrict__ Whh,
                 const float* __restrict__ bih,
                 const float* __restrict__ bhh,
                 const float* __restrict__ Wout,
                 const float* __restrict__ bout,
                 float* __restrict__ out)
{
    extern __shared__ char smem[];
    ull*    Wsm    = (ull*)(smem + OFF_WSM);
    float4* gates4 = (float4*)(smem + OFF_GATES);
    float*  gatesf = (float*)(smem + OFF_GATES);
    float*  predc  = (float*)(smem + OFF_PREDC);
    float*  wout_s = (float*)(smem + OFF_WOUT);
    float*  wih_s  = (float*)(smem + OFF_WIH);
    float*  xqf    = (float*)(smem + OFF_XQ);
    const float4* xq4 = (const float4*)(smem + OFF_XQ);
    float*  pp     = (float*)(smem + OFF_PP);

    const int tid       = threadIdx.x;
    const uint32_t rank = (uint32_t)(blockIdx.x & 1);
    const uint32_t peer = rank ^ 1u;
    const int cluster   = blockIdx.x >> 1;
    const int row0      = cluster * 4;

    const uint32_t smem_b = (uint32_t)__cvta_generic_to_shared(smem);
    const uint32_t mbar_b = smem_b + OFF_MBAR;

    // ---- one-time init: weights into regs + smem ----
    ull wregA[WR], wregB[WR];
    float biasA = 0.f, biasB = 0.f;
    if (tid < 164) {
        int gt  = tid / JH;
        int jj0 = tid - gt * JH;
        int RA  = gt * Hh + (int)rank * JH + jj0;         // gates i/f
        int RB  = (gt + 2) * Hh + (int)rank * JH + jj0;   // gates g/o
        const ull* wrA = (const ull*)(Whh + (size_t)RA * Hh);
        const ull* wrB = (const ull*)(Whh + (size_t)RB * Hh);
#pragma unroll
        for (int kk = 0; kk < WR; kk++) { wregA[kk] = wrA[kk]; wregB[kk] = wrB[kk]; }
        for (int kk = WR; kk < KP; kk++) {
            Wsm[((kk - WR) * 2 + 0) * 164 + tid] = wrA[kk];
            Wsm[((kk - WR) * 2 + 1) * 164 + tid] = wrB[kk];
        }
#pragma unroll
        for (int i = 0; i < Ii; i++) {
            wih_s[tid * Ii + i]         = Wih[RA * Ii + i];
            wih_s[(tid + 164) * Ii + i] = Wih[RB * Ii + i];
        }
        biasA = bih[RA] + bhh[RA];
        biasB = bih[RB] + bhh[RB];
    }
    if (tid < JH) wout_s[tid] = Wout[(int)rank * JH + tid];
    for (int idx = tid; idx < 2 * KP * 8; idx += NTH)
        ((float*)(smem + OFF_HQ))[idx] = 0.f;   // both h buffers -> zeros
    if (tid == 0) {
        asm volatile("mbarrier.init.shared.b64 [%0], 1;" :: "r"(mbar_b) : "memory");
        asm volatile("mbarrier.init.shared.b64 [%0], 1;" :: "r"(mbar_b + 8) : "memory");
    }
    const float bout_r = bout[0];
    float cA = 0.f, cB = 0.f;

    // x prefetch state (tid<32: r=tid>>3, i=tid&7)
    float xn = 0.f; int xrow = 0, xi = 0, xr = 0;
    if (tid < 32) {
        xr = tid >> 3; xi = tid & 7; xrow = row0 + xr;
        xn = x[((size_t)(xrow * Tt)) * Ii + xi];
    }

    __syncthreads();
    asm volatile("barrier.cluster.arrive.aligned;" ::: "memory");
    asm volatile("barrier.cluster.wait.aligned;" ::: "memory");

    for (int t = 0; t < Tt; ++t) {
        const int cur = t & 1;
        const int nxt = cur ^ 1;

        // wait for peer's h-half + pred partial from step t-1
        if (t) mbar_wait(mbar_b + (uint32_t)(((t - 1) & 1) * 8), (uint32_t)(((t - 1) >> 1) & 1));

        // ---- P0: x feed (prefetched), anomaly fix, pred/flag outputs ----
        if (tid < 32) {
            float xv = xn;
            if (xi == 0) {
                float flag = 0.f;
                if (t) {
                    int prev = cur ^ 1;
                    float pred = pp[(prev * 2 + 0) * 4 + xr] + pp[(prev * 2 + 1) * 4 + xr] + bout_r;
                    if (rank == 0) out[(size_t)xrow * Tt + (t - 1)] = pred;   // pred_{t-1}
                    if (fabsf(pred - xv) > 0.1f) { xv = pred; flag = 1.f; }
                }
                if (rank == 0) out[(size_t)Bb * Tt + (size_t)xrow * Tt + t] = flag;
            }
            xqf[xi * 4 + xr] = xv;
            if (t + 1 < Tt) xn = x[((size_t)(xrow * Tt + t + 1)) * Ii + xi];  // prefetch
        }
        __syncthreads();

        // ---- P1: gate accumulation over k-pairs ----
        if (tid < 164) {
            float aA0 = biasA, aA1 = biasA, aA2 = biasA, aA3 = biasA;
            float aB0 = biasB, aB1 = biasB, aB2 = biasB, aB3 = biasB;
#pragma unroll
            for (int i = 0; i < Ii; i++) {
                float4 xv = xq4[i];
                float wA = wih_s[tid * Ii + i];
                float wB = wih_s[(tid + 164) * Ii + i];
                aA0 += wA * xv.x; aA1 += wA * xv.y; aA2 += wA * xv.z; aA3 += wA * xv.w;
                aB0 += wB * xv.x; aB1 += wB * xv.y; aB2 += wB * xv.z; aB3 += wB * xv.w;
            }
            ull accA[4], accB[4];
            accA[0] = pack2_(aA0, 0.f); accA[1] = pack2_(aA1, 0.f);
            accA[2] = pack2_(aA2, 0.f); accA[3] = pack2_(aA3, 0.f);
            accB[0] = pack2_(aB0, 0.f); accB[1] = pack2_(aB1, 0.f);
            accB[2] = pack2_(aB2, 0.f); accB[3] = pack2_(aB3, 0.f);

            const ulonglong2* hp = (const ulonglong2*)(smem + OFF_HQ + cur * (KP * 32));
#pragma unroll
            for (int kk = 0; kk < WR; kk++) {
                ulonglong2 h01 = hp[2 * kk];
                ulonglong2 h23 = hp[2 * kk + 1];
                fma2_(accA[0], wregA[kk], h01.x); fma2_(accB[0], wregB[kk], h01.x);
                fma2_(accA[1], wregA[kk], h01.y); fma2_(accB[1], wregB[kk], h01.y);
                fma2_(accA[2], wregA[kk], h23.x); fma2_(accB[2], wregB[kk], h23.x);
                fma2_(accA[3], wregA[kk], h23.y); fma2_(accB[3], wregB[kk], h23.y);
            }
#pragma unroll 7
            for (int kk = WR; kk < KP; kk++) {
                ull wA = Wsm[((kk - WR) * 2 + 0) * 164 + tid];
                ull wB = Wsm[((kk - WR) * 2 + 1) * 164 + tid];
                ulonglong2 h01 = hp[2 * kk];
                ulonglong2 h23 = hp[2 * kk + 1];
                fma2_(accA[0], wA, h01.x); fma2_(accB[0], wB, h01.x);
                fma2_(accA[1], wA, h01.y); fma2_(accB[1], wB, h01.y);
                fma2_(accA[2], wA, h23.x); fma2_(accB[2], wB, h23.x);
                fma2_(accA[3], wA, h23.y); fma2_(accB[3], wB, h23.y);
            }
            float lo, hi, g0, g1, g2, g3;
            unpack2_(accA[0], lo, hi); g0 = lo + hi;
            unpack2_(accA[1], lo, hi); g1 = lo + hi;
            unpack2_(accA[2], lo, hi); g2 = lo + hi;
            unpack2_(accA[3], lo, hi); g3 = lo + hi;
            gates4[tid] = make_float4(g0, g1, g2, g3);
            unpack2_(accB[0], lo, hi); g0 = lo + hi;
            unpack2_(accB[1], lo, hi); g1 = lo + hi;
            unpack2_(accB[2], lo, hi); g2 = lo + hi;
            unpack2_(accB[3], lo, hi); g3 = lo + hi;
            gates4[tid + 164] = make_float4(g0, g1, g2, g3);
        }
        __syncthreads();

        // ---- P2: activations, (c,h) update, h exchange, pred contributions ----
        if (tid < 164) {
#pragma unroll
            for (int slot = 0; slot < 2; slot++) {
                int s  = tid + slot * 164;
                int jj = s >> 2, r = s & 3;
                float gi = gatesf[(0 * JH + jj) * 4 + r];
                float gF = gatesf[(1 * JH + jj) * 4 + r];
                float gg = gatesf[(2 * JH + jj) * 4 + r];
                float go = gatesf[(3 * JH + jj) * 4 + r];
                float iv = sigmoidf_(gi);
                float fv = sigmoidf_(gF);
                float gv = tanhf(gg);
                float ov = sigmoidf_(go);
                float c  = (slot == 0) ? cA : cB;
                c = fv * c + iv * gv;
                float hn = ov * tanhf(c);
                if (slot == 0) cA = c; else cB = c;

                int kg = (int)rank * JH + jj;
                uint32_t hoff = (uint32_t)(OFF_HQ + nxt * (KP * 32) + (kg >> 1) * 32 + r * 8 + (kg & 1) * 4);
                *(float*)(smem + hoff) = hn;
                st_remote_f32(smem_b + hoff, peer, hn);
                predc[s] = hn * wout_s[jj];
            }
        }
        __syncthreads();

        // ---- P3: per-row pred partial reduction (4 warps) ----
        if (tid < 128) {
            int r = tid >> 5, lane = tid & 31;
            float s = 0.f;
            for (int jj = lane; jj < JH; jj += 32) s += predc[jj * 4 + r];
#pragma unroll
            for (int o = 16; o > 0; o >>= 1) s += __shfl_down_sync(0xffffffffu, s, o);
            if (lane == 0) {
                int pidx = (cur * 2 + (int)rank) * 4 + r;
                pp[pidx] = s;
                st_remote_f32(smem_b + OFF_PP + (uint32_t)(pidx * 4), peer, s);
            }
        }
        __syncthreads();

        // signal peer: my remote stores for step t are done
        if (tid == 0) mbar_arrive_peer(mbar_b + (uint32_t)(cur * 8), peer);
    }

    // ---- tail: final prediction (column Tt-1) ----
    mbar_wait(mbar_b + (uint32_t)(((Tt - 1) & 1) * 8), (uint32_t)(((Tt - 1) >> 1) & 1));
    if (rank == 0 && tid < 4) {
        int prev = (Tt - 1) & 1;
        float pred = pp[(prev * 2 + 0) * 4 + tid] + pp[(prev * 2 + 1) * 4 + tid] + bout_r;
        out[(size_t)(row0 + tid) * Tt + (Tt - 1)] = pred;
    }
}

extern "C" void kernel_launch(void* const* d_in, const int* in_sizes, int n_in,
                              void* d_out, int out_size) {
    (void)in_sizes; (void)n_in; (void)out_size;
    cudaFuncSetAttribute(lstm_anom_kernel,
                         cudaFuncAttributeMaxDynamicSharedMemorySize, SMEM_TOTAL);
    lstm_anom_kernel<<<NCTA, NTH, SMEM_TOTAL>>>(
        (const float*)d_in[0],   // x
        (const float*)d_in[1],   // W_ih
        (const float*)d_in[2],   // W_hh
        (const float*)d_in[3],   // b_ih
        (const float*)d_in[4],   // b_hh
        (const float*)d_in[5],   // W_out
        (const float*)d_in[6],   // b_out
        (float*)d_out);
}

// round 3
// speedup vs baseline: 1.3288x; 1.2551x over previous
#include <cuda_runtime.h>
#include <cstdint>
#include <math.h>

// Problem constants
#define Bb   256
#define Tt   1024
#define Ii   8
#define Hh   164
#define JH   82          // hidden slice per CTA (M-split across 2-CTA cluster)
#define KH   41          // k-pairs per K-half
#define RKK  24          // k-pairs kept in registers
#define SKK  (KH - RKK)  // 17 k-pairs in smem
#define CT   328         // compute threads (164 gate-row-pairs x 2 k-halves)
#define NTH  352         // 11 warps (24 spare threads overlap pred/x work)
#define NCTA 128         // 64 clusters x 2

// shared memory layout (bytes)
#define OFF_WSM   0
#define SZ_WSM    (SKK * 2 * CT * 8)        // 89216: Wsm[kks][AB][ct] u64
#define OFF_HQ    (OFF_WSM + SZ_WSM)
#define SZ_HQ     (2 * JH * 32)             // 5248: h double-buffered, 32B/k-pair
#define OFF_GB    (OFF_HQ + SZ_HQ)
#define SZ_GB     (4 * 164 * 16)            // 10496: gate partials float4[ab*2+half][g]
#define OFF_PW    (OFF_GB + SZ_GB)
#define SZ_PW     (2 * 2 * 12 * 16)         // 768: pred warp partials [par][side][w][r]
#define OFF_XQ    (OFF_PW + SZ_PW)
#define SZ_XQ     (2 * Ii * 16)             // 256: x double-buffered [par][i][r]
#define OFF_MBAR  (OFF_XQ + SZ_XQ)
#define SZ_MBAR   16
#define SMEM_TOTAL (OFF_MBAR + SZ_MBAR)     // ~106KB

typedef unsigned long long ull;

__device__ __forceinline__ float sigmoidf_(float v) {
    return 1.0f / (1.0f + expf(-v));
}
__device__ __forceinline__ ull pack2_(float a, float b) {
    ull r; asm("mov.b64 %0, {%1, %2};" : "=l"(r) : "f"(a), "f"(b)); return r;
}
__device__ __forceinline__ void unpack2_(ull v, float& a, float& b) {
    asm("mov.b64 {%0, %1}, %2;" : "=f"(a), "=f"(b) : "l"(v));
}
__device__ __forceinline__ void fma2_(ull& acc, ull a, ull b) {
    asm("fma.rn.f32x2 %0, %1, %2, %0;" : "+l"(acc) : "l"(a), "l"(b));
}
__device__ __forceinline__ void st_remote_f32(uint32_t local_addr, uint32_t peer, float v) {
    uint32_t ra;
    asm("mapa.shared::cluster.u32 %0, %1, %2;" : "=r"(ra) : "r"(local_addr), "r"(peer));
    asm volatile("st.shared::cluster.f32 [%0], %1;" :: "r"(ra), "f"(v) : "memory");
}
__device__ __forceinline__ void mbar_arrive_peer(uint32_t local_mbar, uint32_t peer) {
    asm volatile(
        "{\n\t.reg .b32 ra;\n\t"
        "mapa.shared::cluster.u32 ra, %0, %1;\n\t"
        "mbarrier.arrive.release.cluster.shared::cluster.b64 _, [ra];\n\t}"
        :: "r"(local_mbar), "r"(peer) : "memory");
}
__device__ __forceinline__ void mbar_wait(uint32_t mbar, uint32_t parity) {
    uint32_t done;
    asm volatile(
        "{\n\t.reg .pred p;\n\t"
        "mbarrier.try_wait.parity.acquire.cluster.shared::cta.b64 p, [%1], %2;\n\t"
        "selp.b32 %0, 1, 0, p;\n\t}"
        : "=r"(done) : "r"(mbar), "r"(parity) : "memory");
    while (!done) {
        asm volatile(
            "{\n\t.reg .pred p;\n\t"
            "mbarrier.try_wait.parity.acquire.cluster.shared::cta.b64 p, [%1], %2, 0x989680;\n\t"
            "selp.b32 %0, 1, 0, p;\n\t}"
            : "=r"(done) : "r"(mbar), "r"(parity) : "memory");
    }
}

extern "C" __global__ void __launch_bounds__(NTH, 1) __cluster_dims__(2, 1, 1)
lstm_anom_kernel(const float* __restrict__ x,
                 const float* __restrict__ Wih,
                 const float* __restrict__ Whh,
                 const float* __restrict__ bih,
                 const float* __restrict__ bhh,
                 const float* __restrict__ Wout,
                 const float* __restrict__ bout,
                 float* __restrict__ out)
{
    extern __shared__ char smem[];
    ull*    Wsm  = (ull*)(smem + OFF_WSM);
    float4* gb4  = (float4*)(smem + OFF_GB);
    const float* gbf = (const float*)(smem + OFF_GB);
    float*  pwf  = (float*)(smem + OFF_PW);
    float*  xqf  = (float*)(smem + OFF_XQ);

    const int tid       = threadIdx.x;
    const uint32_t rank = (uint32_t)(blockIdx.x & 1);
    const uint32_t peer = rank ^ 1u;
    const int cluster   = blockIdx.x >> 1;
    const int row0      = cluster * 4;

    const uint32_t smem_b = (uint32_t)__cvta_generic_to_shared(smem);
    const uint32_t mbar_b = smem_b + OFF_MBAR;

    // ---------- one-time init ----------
    // GEMV role: g = row-pair id (0..163), half = k-half
    const int g    = (tid < 164) ? tid : tid - 164;
    const int half = (tid < 164) ? 0 : 1;
    const int gt   = g / JH;
    const int jj0  = g - gt * JH;
    const int RA   = gt * Hh + (int)rank * JH + jj0;        // i or f gate row
    const int RB   = (gt + 2) * Hh + (int)rank * JH + jj0;  // g or o gate row

    ull wregA[RKK], wregB[RKK];
    float wihA[7], wihB[7], biasA = 0.f, biasB = 0.f;
    if (tid < CT) {
        const ull* wrA = (const ull*)(Whh + (size_t)RA * Hh) + half * KH;
        const ull* wrB = (const ull*)(Whh + (size_t)RB * Hh) + half * KH;
#pragma unroll
        for (int kk = 0; kk < RKK; kk++) { wregA[kk] = wrA[kk]; wregB[kk] = wrB[kk]; }
        for (int kk = RKK; kk < KH; kk++) {
            Wsm[((kk - RKK) * 2 + 0) * CT + tid] = wrA[kk];
            Wsm[((kk - RKK) * 2 + 1) * CT + tid] = wrB[kk];
        }
        if (half == 0) {
#pragma unroll
            for (int i = 1; i < Ii; i++) {
                wihA[i - 1] = Wih[RA * Ii + i];
                wihB[i - 1] = Wih[RB * Ii + i];
            }
            biasA = bih[RA] + bhh[RA];
            biasB = bih[RB] + bhh[RB];
        }
    }
    // activation role: slot s = tid (<CT): jj = s>>2, r = s&3
    const int jj = tid >> 2, rr = tid & 3;
    float wih0i = 0.f, wih0f = 0.f, wih0g = 0.f, wih0o = 0.f, wout_r = 0.f;
    if (tid < CT) {
        int base = (int)rank * JH + jj;
        wih0i = Wih[(0 * Hh + base) * Ii];
        wih0f = Wih[(1 * Hh + base) * Ii];
        wih0g = Wih[(2 * Hh + base) * Ii];
        wih0o = Wih[(3 * Hh + base) * Ii];
        wout_r = Wout[base];
    }
    float c_r = 0.f;
    const float bout_r = bout[0];

    // zero h (both buffers) and pred-warp partials (both parities)
    for (int idx = tid; idx < (SZ_HQ / 4); idx += NTH)
        ((float*)(smem + OFF_HQ))[idx] = 0.f;
    for (int idx = tid; idx < (SZ_PW / 4); idx += NTH) pwf[idx] = 0.f;
    // x(0) into parity 0
    if (tid < 32) {
        int i = tid >> 2, r = tid & 3;
        xqf[(0 * Ii + i) * 4 + r] = x[((size_t)((row0 + r) * Tt)) * Ii + i];
    }
    if (tid == 0) {
        asm volatile("mbarrier.init.shared.b64 [%0], 1;" :: "r"(mbar_b) : "memory");
        asm volatile("mbarrier.init.shared.b64 [%0], 1;" :: "r"(mbar_b + 8) : "memory");
    }
    __syncthreads();
    asm volatile("barrier.cluster.arrive.aligned;" ::: "memory");
    asm volatile("barrier.cluster.wait.aligned;" ::: "memory");

    const int wid = tid >> 5, lane = tid & 31;

    for (int t = 0; t < Tt; ++t) {
        const int cur = t & 1;
        const int nxt = cur ^ 1;

        // wait for peer's h-half + pred warp-partials of step t-1
        if (t) mbar_wait(mbar_b + (uint32_t)(((t - 1) & 1) * 8), (uint32_t)(((t - 1) >> 1) & 1));

        if (tid < CT) {
            // ---- GEMV over own k-half ----
            ull accA[4], accB[4];
            if (half == 0) {
                float a0 = biasA, a1 = biasA, a2 = biasA, a3 = biasA;
                float b0 = biasB, b1 = biasB, b2 = biasB, b3 = biasB;
                const float4* xv4 = (const float4*)(smem + OFF_XQ + cur * 128);
#pragma unroll
                for (int i = 1; i < Ii; i++) {
                    float4 xv = xv4[i];
                    float wA = wihA[i - 1], wB = wihB[i - 1];
                    a0 += wA * xv.x; a1 += wA * xv.y; a2 += wA * xv.z; a3 += wA * xv.w;
                    b0 += wB * xv.x; b1 += wB * xv.y; b2 += wB * xv.z; b3 += wB * xv.w;
                }
                accA[0] = pack2_(a0, 0.f); accA[1] = pack2_(a1, 0.f);
                accA[2] = pack2_(a2, 0.f); accA[3] = pack2_(a3, 0.f);
                accB[0] = pack2_(b0, 0.f); accB[1] = pack2_(b1, 0.f);
                accB[2] = pack2_(b2, 0.f); accB[3] = pack2_(b3, 0.f);
            } else {
#pragma unroll
                for (int q = 0; q < 4; q++) { accA[q] = 0ull; accB[q] = 0ull; }
            }
            const ulonglong2* hp =
                (const ulonglong2*)(smem + OFF_HQ + cur * (JH * 32) + half * (KH * 32));
#pragma unroll
            for (int kk = 0; kk < RKK; kk++) {
                ulonglong2 h01 = hp[2 * kk];
                ulonglong2 h23 = hp[2 * kk + 1];
                fma2_(accA[0], wregA[kk], h01.x); fma2_(accB[0], wregB[kk], h01.x);
                fma2_(accA[1], wregA[kk], h01.y); fma2_(accB[1], wregB[kk], h01.y);
                fma2_(accA[2], wregA[kk], h23.x); fma2_(accB[2], wregB[kk], h23.x);
                fma2_(accA[3], wregA[kk], h23.y); fma2_(accB[3], wregB[kk], h23.y);
            }
#pragma unroll
            for (int kk = RKK; kk < KH; kk++) {
                ull wA = Wsm[((kk - RKK) * 2 + 0) * CT + tid];
                ull wB = Wsm[((kk - RKK) * 2 + 1) * CT + tid];
                ulonglong2 h01 = hp[2 * kk];
                ulonglong2 h23 = hp[2 * kk + 1];
                fma2_(accA[0], wA, h01.x); fma2_(accB[0], wB, h01.x);
                fma2_(accA[1], wA, h01.y); fma2_(accB[1], wB, h01.y);
                fma2_(accA[2], wA, h23.x); fma2_(accB[2], wB, h23.x);
                fma2_(accA[3], wA, h23.y); fma2_(accB[3], wB, h23.y);
            }
            float lo, hi;
            float4 vA, vB;
            unpack2_(accA[0], lo, hi); vA.x = lo + hi;
            unpack2_(accA[1], lo, hi); vA.y = lo + hi;
            unpack2_(accA[2], lo, hi); vA.z = lo + hi;
            unpack2_(accA[3], lo, hi); vA.w = lo + hi;
            unpack2_(accB[0], lo, hi); vB.x = lo + hi;
            unpack2_(accB[1], lo, hi); vB.y = lo + hi;
            unpack2_(accB[2], lo, hi); vB.z = lo + hi;
            unpack2_(accB[3], lo, hi); vB.w = lo + hi;
            gb4[(0 * 2 + half) * 164 + g] = vA;
            gb4[(1 * 2 + half) * 164 + g] = vB;
        } else {
            // ---- spare threads: pred finalize, anomaly fix, x prefetch ----
            int sp = tid - CT;
            if (sp < 4) {
                int r = sp, row = row0 + r;
                int prev = cur ^ 1;
                if (t > 0) {
                    float pred = bout_r;
#pragma unroll
                    for (int w = 0; w < 11; w++) {
                        pred += pwf[((prev * 2 + 0) * 12 + w) * 4 + r];
                        pred += pwf[((prev * 2 + 1) * 12 + w) * 4 + r];
                    }
                    float x0raw = xqf[(cur * Ii + 0) * 4 + r];
                    float flag = 0.f, x0 = x0raw;
                    if (fabsf(pred - x0raw) > 0.1f) { x0 = pred; flag = 1.f; }
                    xqf[(cur * Ii + 0) * 4 + r] = x0;
                    if (rank == 0) {
                        out[(size_t)row * Tt + (t - 1)] = pred;
                        out[(size_t)Bb * Tt + (size_t)row * Tt + t] = flag;
                    }
                    // reset consumed pred partials for reuse at step t+1
#pragma unroll
                    for (int w = 0; w < 11; w++) {
                        pwf[((prev * 2 + 0) * 12 + w) * 4 + r] = 0.f;
                        pwf[((prev * 2 + 1) * 12 + w) * 4 + r] = 0.f;
                    }
                } else {
                    if (rank == 0)
                        out[(size_t)Bb * Tt + (size_t)row * Tt + 0] = 0.f;
                }
            } else if (sp >= 8 && sp < 24 && (t + 1 < Tt)) {
                int pi = sp - 8;
#pragma unroll
                for (int q = 0; q < 2; q++) {
                    int p = pi + q * 16;
                    int i = p >> 2, r = p & 3;
                    xqf[(nxt * Ii + i) * 4 + r] =
                        x[((size_t)((row0 + r) * Tt + t + 1)) * Ii + i];
                }
            }
        }
        __syncthreads();   // gate partials + fixed x0 published

        // ---- activation, state update, h exchange, pred partials ----
        if (tid < CT) {
            float x0 = xqf[(cur * Ii + 0) * 4 + rr];
            float gi = gbf[((0 * 2 + 0) * 164 + jj) * 4 + rr]
                     + gbf[((0 * 2 + 1) * 164 + jj) * 4 + rr] + wih0i * x0;
            float gF = gbf[((0 * 2 + 0) * 164 + jj + 82) * 4 + rr]
                     + gbf[((0 * 2 + 1) * 164 + jj + 82) * 4 + rr] + wih0f * x0;
            float gg = gbf[((1 * 2 + 0) * 164 + jj) * 4 + rr]
                     + gbf[((1 * 2 + 1) * 164 + jj) * 4 + rr] + wih0g * x0;
            float go = gbf[((1 * 2 + 0) * 164 + jj + 82) * 4 + rr]
                     + gbf[((1 * 2 + 1) * 164 + jj + 82) * 4 + rr] + wih0o * x0;
            float iv = sigmoidf_(gi);
            float fv = sigmoidf_(gF);
            float gv = tanhf(gg);
            float ov = sigmoidf_(go);
            c_r = fv * c_r + iv * gv;
            float hn = ov * tanhf(c_r);

            int kg = (int)rank * JH + jj;
            uint32_t hoff = (uint32_t)(OFF_HQ + nxt * (JH * 32)
                                       + (kg >> 1) * 32 + rr * 8 + (kg & 1) * 4);
            *(float*)(smem + hoff) = hn;
            st_remote_f32(smem_b + hoff, peer, hn);

            // pred partial: reduce over jj within warp (lanes grouped by r = lane&3)
            float p = hn * wout_r;
            if (wid < 10) {
                p += __shfl_xor_sync(0xffffffffu, p, 16);
                p += __shfl_xor_sync(0xffffffffu, p, 8);
                p += __shfl_xor_sync(0xffffffffu, p, 4);
            } else {
                p += __shfl_xor_sync(0xffu, p, 4);   // warp 10: lanes 0-7 only
            }
            if (lane < 4) {
                uint32_t po0 = (uint32_t)(OFF_PW + (((cur * 2 + 0) * 12 + wid) * 4 + lane) * 4);
                uint32_t po1 = (uint32_t)(OFF_PW + (((cur * 2 + 1) * 12 + wid) * 4 + lane) * 4);
                *(float*)(smem + po0) = p;            // local, side 0 = own warps
                st_remote_f32(smem_b + po1, peer, p); // peer, side 1 = my warps
            }
        }
        __syncthreads();   // local h/pw writes complete; remote STS drained by BAR

        if (tid == 0) mbar_arrive_peer(mbar_b + (uint32_t)(cur * 8), peer);
    }

    // ---- tail: final prediction at column Tt-1 ----
    mbar_wait(mbar_b + (uint32_t)(((Tt - 1) & 1) * 8), (uint32_t)(((Tt - 1) >> 1) & 1));
    if (rank == 0 && tid < 4) {
        int par = (Tt - 1) & 1;
        float pred = bout_r;
#pragma unroll
        for (int w = 0; w < 11; w++) {
            pred += pwf[((par * 2 + 0) * 12 + w) * 4 + tid];
            pred += pwf[((par * 2 + 1) * 12 + w) * 4 + tid];
        }
        out[(size_t)(row0 + tid) * Tt + (Tt - 1)] = pred;
    }
}

extern "C" void kernel_launch(void* const* d_in, const int* in_sizes, int n_in,
                              void* d_out, int out_size) {
    (void)in_sizes; (void)n_in; (void)out_size;
    cudaFuncSetAttribute(lstm_anom_kernel,
                         cudaFuncAttributeMaxDynamicSharedMemorySize, SMEM_TOTAL);
    lstm_anom_kernel<<<NCTA, NTH, SMEM_TOTAL>>>(
        (const float*)d_in[0],   // x
        (const float*)d_in[1],   // W_ih
        (const float*)d_in[2],   // W_hh
        (const float*)d_in[3],   // b_ih
        (const float*)d_in[4],   // b_hh
        (const float*)d_in[5],   // W_out
        (const float*)d_in[6],   // b_out
        (float*)d_out);
}